// round 4
// baseline (speedup 1.0000x reference)
#include <cuda_runtime.h>
#include <cuda_bf16.h>
#include <stdint.h>

#define N_NODES 50000
#define N_EDGES 800000

// ---------------- scratch (device globals; no allocation allowed) ----------
__device__ int   g_is64;
__device__ int   g_deg[N_NODES];
__device__ int   g_rowptr[N_NODES + 1];
__device__ int   g_rowcur[N_NODES];
__device__ int   g_colidx[N_EDGES];
__device__ int   g_bsum[64];
__device__ float g_dis[N_NODES];
__device__ float g_feat[N_NODES * 64];   // ping
__device__ float g_agg [N_NODES * 64];   // pong
__device__ float g_actA[N_NODES * 128];
__device__ float g_actB[N_NODES * 128];

// ---------------- packed f32x2 helpers (Blackwell) ---------------------------
__device__ __forceinline__ unsigned long long pack2(float x, float y) {
    unsigned long long r;
    asm("mov.b64 %0, {%1, %2};" : "=l"(r) : "f"(x), "f"(y));
    return r;
}
__device__ __forceinline__ void unpack2(unsigned long long v, float& x, float& y) {
    asm("mov.b64 {%0, %1}, %2;" : "=f"(x), "=f"(y) : "l"(v));
}
__device__ __forceinline__ unsigned long long fma2(unsigned long long a,
                                                   unsigned long long b,
                                                   unsigned long long c) {
    unsigned long long d;
    asm("fma.rn.f32x2 %0, %1, %2, %3;" : "=l"(d) : "l"(a), "l"(b), "l"(c));
    return d;
}

// ---------------- init: zero degrees + dtype probe ---------------------------
__global__ void k_init(const void* __restrict__ ei) {
    int i = blockIdx.x * blockDim.x + threadIdx.x;
    if (i < N_NODES) g_deg[i] = 0;
    if (i == 0) {
        const long long* p = (const long long*)ei;
        int ok64 = 1;
        for (int q = 0; q < 64; q++) {
            long long v = p[q];
            if (v < 0 || v >= N_NODES) { ok64 = 0; break; }
        }
        g_is64 = ok64;
    }
}

__device__ __forceinline__ int edge_at(const void* ei, long long idx) {
    if (g_is64) return (int)((const long long*)ei)[idx];
    return ((const int*)ei)[idx];
}

// ---------------- CSR build -------------------------------------------------
__global__ void k_hist(const void* __restrict__ ei) {
    int e = blockIdx.x * blockDim.x + threadIdx.x;
    if (e < N_EDGES) {
        int d = edge_at(ei, (long long)N_EDGES + e);
        if (d >= 0 && d < N_NODES) atomicAdd(&g_deg[d], 1);
    }
}

// shuffle-based block scan (1024 threads)
__global__ void k_scan1() {
    __shared__ int ws[32];
    int i = blockIdx.x * 1024 + threadIdx.x;
    int v = (i < N_NODES) ? g_deg[i] : 0;
    int incl = v;
    int lane = threadIdx.x & 31, wid = threadIdx.x >> 5;
#pragma unroll
    for (int off = 1; off < 32; off <<= 1) {
        int t = __shfl_up_sync(0xffffffffu, incl, off);
        if (lane >= off) incl += t;
    }
    if (lane == 31) ws[wid] = incl;
    __syncthreads();
    if (threadIdx.x < 32) {
        int s = ws[threadIdx.x];
        int si = s;
#pragma unroll
        for (int off = 1; off < 32; off <<= 1) {
            int t = __shfl_up_sync(0xffffffffu, si, off);
            if (threadIdx.x >= off) si += t;
        }
        ws[threadIdx.x] = si - s;  // exclusive warp offset
    }
    __syncthreads();
    int excl = incl - v + ws[wid];
    if (i < N_NODES) g_rowptr[i] = excl;
    if (threadIdx.x == 1023) g_bsum[blockIdx.x] = excl + v;
}

__global__ void k_scan2(int nb) {
    __shared__ int s[64];
    int v = (threadIdx.x < nb) ? g_bsum[threadIdx.x] : 0;
    s[threadIdx.x] = v;
    __syncthreads();
    for (int off = 1; off < 64; off <<= 1) {
        int t = (threadIdx.x >= off) ? s[threadIdx.x - off] : 0;
        __syncthreads();
        s[threadIdx.x] += t;
        __syncthreads();
    }
    if (threadIdx.x < nb) g_bsum[threadIdx.x] = s[threadIdx.x] - v;
}

__global__ void k_scan3() {
    int i = blockIdx.x * blockDim.x + threadIdx.x;
    if (i < N_NODES) {
        int r = g_rowptr[i] + g_bsum[i >> 10];
        g_rowptr[i] = r;
        g_rowcur[i] = r;
        g_dis[i]    = rsqrtf((float)(g_deg[i] + 1));
    }
    if (i == 0) g_rowptr[N_NODES] = N_EDGES;
}

__global__ void k_scatter(const void* __restrict__ ei) {
    int e = blockIdx.x * blockDim.x + threadIdx.x;
    if (e < N_EDGES) {
        int s = edge_at(ei, e);
        int d = edge_at(ei, (long long)N_EDGES + e);
        if (d >= 0 && d < N_NODES && s >= 0 && s < N_NODES) {
            int p = atomicAdd(&g_rowcur[d], 1);
            g_colidx[p] = s;
        }
    }
}

// ---------------- fused conv: gather + GEMM + bias + relu (+dis) ------------
// G rows are dis-pre-scaled features (or raw x with SCIN=true).
// out[n,:] = relu( [dis[n]*(G[n]+sum_src G[src])] @ W + b ) * (SCOUT ? dis[n] : 1)
template <int DIN, int DOUT, bool SCIN, bool SCOUT>
__global__ void __launch_bounds__(256) k_conv(
        const float* __restrict__ G,
        const float* __restrict__ W,
        const float* __restrict__ b,
        float* __restrict__ out) {
    constexpr int NB  = 64;
    constexpr int TN  = 8;
    constexpr int TX  = DOUT / TN;                  // 4, 8, 16
    constexpr int TY  = 256 / TX;                   // 64, 32, 16
    constexpr int TM  = NB / TY;                    // 1, 2, 4
    constexpr int KC  = (DIN * DOUT >= 8192) ? 32 : DIN;
    constexpr int NKC = DIN / KC;
    constexpr int INP = DIN + 2;                    // even pad: float2-aligned rows
    constexpr int SWW = DOUT + 2 * (DOUT / 32) + 2;

    __shared__ float inS[NB * INP];
    __shared__ float Ws[KC * SWW];

    const int tid   = threadIdx.x;
    const int node0 = blockIdx.x * NB;
    const int wid   = tid >> 5;
    const int lane  = tid & 31;
    const int tx    = tid % TX;
    const int ty    = tid / TX;

    // bias
    float bb[TN];
#pragma unroll
    for (int j = 0; j < TN; j++) bb[j] = __ldg(&b[tx * TN + j]);

    // stage weight chunk 0
    {
        const int k0 = 0;
        for (int i = tid; i < KC * DOUT; i += 256) {
            int r = i / DOUT, c = i - r * DOUT;
            Ws[r * SWW + c + 2 * (c >> 5)] = __ldg(&W[(size_t)(k0 + r) * DOUT + c]);
        }
    }

    // ---- gather phase: warp wid owns nodes [wid*8, wid*8+8) of this block ----
    if constexpr (DIN == 16) {
        int sub = lane >> 4, l16 = lane & 15;
#pragma unroll
        for (int ii = 0; ii < 4; ii++) {
            int r = wid * 8 + ii * 2 + sub;
            int n = node0 + r;
            float acc = 0.f;
            if (n < N_NODES) {
                float self = __ldg(&G[n * 16 + l16]);
                acc = SCIN ? self * __ldg(&g_dis[n]) : self;
                int p = g_rowptr[n], end = g_rowptr[n + 1];
                for (; p + 2 <= end; p += 2) {
                    int s0 = g_colidx[p], s1 = g_colidx[p + 1];
                    float v0 = __ldg(&G[s0 * 16 + l16]);
                    float v1 = __ldg(&G[s1 * 16 + l16]);
                    if (SCIN) {
                        v0 *= __ldg(&g_dis[s0]);
                        v1 *= __ldg(&g_dis[s1]);
                    }
                    acc += v0 + v1;
                }
                if (p < end) {
                    int s0 = g_colidx[p];
                    float v0 = __ldg(&G[s0 * 16 + l16]);
                    if (SCIN) v0 *= __ldg(&g_dis[s0]);
                    acc += v0;
                }
                acc *= __ldg(&g_dis[n]);
            }
            inS[r * INP + l16] = acc;
        }
    } else if constexpr (DIN == 32) {
#pragma unroll
        for (int ii = 0; ii < 8; ii++) {
            int r = wid * 8 + ii;
            int n = node0 + r;
            float acc = 0.f;
            if (n < N_NODES) {
                acc = __ldg(&G[(size_t)n * 32 + lane]);
                int p = g_rowptr[n], end = g_rowptr[n + 1];
                for (; p + 4 <= end; p += 4) {
                    int s0 = g_colidx[p], s1 = g_colidx[p + 1];
                    int s2 = g_colidx[p + 2], s3 = g_colidx[p + 3];
                    acc += __ldg(&G[(size_t)s0 * 32 + lane]);
                    acc += __ldg(&G[(size_t)s1 * 32 + lane]);
                    acc += __ldg(&G[(size_t)s2 * 32 + lane]);
                    acc += __ldg(&G[(size_t)s3 * 32 + lane]);
                }
                for (; p < end; p++)
                    acc += __ldg(&G[(size_t)g_colidx[p] * 32 + lane]);
                acc *= __ldg(&g_dis[n]);
            }
            inS[r * INP + lane] = acc;
        }
    } else {  // DIN == 64
        const float2* G2 = (const float2*)G;
#pragma unroll
        for (int ii = 0; ii < 8; ii++) {
            int r = wid * 8 + ii;
            int n = node0 + r;
            float2 acc = make_float2(0.f, 0.f);
            if (n < N_NODES) {
                acc = __ldg(&G2[(size_t)n * 32 + lane]);
                int p = g_rowptr[n], end = g_rowptr[n + 1];
                for (; p + 4 <= end; p += 4) {
                    int s0 = g_colidx[p], s1 = g_colidx[p + 1];
                    int s2 = g_colidx[p + 2], s3 = g_colidx[p + 3];
                    float2 v0 = __ldg(&G2[(size_t)s0 * 32 + lane]);
                    float2 v1 = __ldg(&G2[(size_t)s1 * 32 + lane]);
                    float2 v2 = __ldg(&G2[(size_t)s2 * 32 + lane]);
                    float2 v3 = __ldg(&G2[(size_t)s3 * 32 + lane]);
                    acc.x += v0.x + v1.x + v2.x + v3.x;
                    acc.y += v0.y + v1.y + v2.y + v3.y;
                }
                for (; p < end; p++) {
                    float2 v = __ldg(&G2[(size_t)g_colidx[p] * 32 + lane]);
                    acc.x += v.x; acc.y += v.y;
                }
                float dd = __ldg(&g_dis[n]);
                acc.x *= dd; acc.y *= dd;
            }
            ((float2*)(inS + r * INP))[lane] = acc;
        }
    }
    __syncthreads();

    // ---- GEMM phase ----
    unsigned long long acc[TM][TN / 2];
#pragma unroll
    for (int m = 0; m < TM; m++)
#pragma unroll
        for (int j = 0; j < TN / 2; j++) acc[m][j] = 0ull;

    for (int kc = 0;;) {
        const int kbase = kc * KC;
#pragma unroll
        for (int k = 0; k < KC; k++) {
            unsigned long long a2[TM];
#pragma unroll
            for (int m = 0; m < TM; m++) {
                float a = inS[(ty * TM + m) * INP + kbase + k];
                a2[m] = pack2(a, a);
            }
#pragma unroll
            for (int j = 0; j < TN / 2; j++) {
                int c = tx * TN + 2 * j;
                float2 wv = *reinterpret_cast<const float2*>(
                    &Ws[k * SWW + c + 2 * (c >> 5)]);
                unsigned long long w2 = pack2(wv.x, wv.y);
#pragma unroll
                for (int m = 0; m < TM; m++)
                    acc[m][j] = fma2(a2[m], w2, acc[m][j]);
            }
        }
        if (++kc == NKC) break;
        __syncthreads();
        const int k0 = kc * KC;
        for (int i = tid; i < KC * DOUT; i += 256) {
            int r = i / DOUT, c = i - r * DOUT;
            Ws[r * SWW + c + 2 * (c >> 5)] = __ldg(&W[(size_t)(k0 + r) * DOUT + c]);
        }
        __syncthreads();
    }

    // ---- epilogue ----
#pragma unroll
    for (int m = 0; m < TM; m++) {
        int node = node0 + ty * TM + m;
        if (node >= N_NODES) continue;
        float sc = SCOUT ? __ldg(&g_dis[node]) : 1.f;
        float vals[TN];
#pragma unroll
        for (int j = 0; j < TN / 2; j++) {
            float v0, v1;
            unpack2(acc[m][j], v0, v1);
            v0 += bb[2 * j];     v1 += bb[2 * j + 1];
            v0 = v0 > 0.f ? v0 : 0.f;
            v1 = v1 > 0.f ? v1 : 0.f;
            vals[2 * j]     = v0 * sc;
            vals[2 * j + 1] = v1 * sc;
        }
        float4* o = (float4*)(out + (size_t)node * DOUT + tx * TN);
#pragma unroll
        for (int q = 0; q < TN / 4; q++)
            o[q] = make_float4(vals[4 * q], vals[4 * q + 1],
                               vals[4 * q + 2], vals[4 * q + 3]);
    }
}

// ---------------- register-tiled GEMM (dense l1: 128 -> 64) -----------------
template <int DIN, int DOUT, bool SCALE>
__global__ void __launch_bounds__(256) k_gemm2(
        const float* __restrict__ in,
        const float* __restrict__ W,
        const float* __restrict__ b,
        float* __restrict__ out) {
    constexpr int NB  = 64;
    constexpr int TN  = 8;
    constexpr int TX  = DOUT / TN;
    constexpr int TY  = 256 / TX;
    constexpr int TM  = NB / TY;
    constexpr int KC  = (DIN * DOUT >= 8192) ? 32 : DIN;
    constexpr int NKC = DIN / KC;
    constexpr int INP = KC + 1;
    constexpr int SWW = DOUT + 2 * (DOUT / 32) + 2;

    __shared__ float inS[NB * INP];
    __shared__ float Ws[KC * SWW];

    const int tid  = threadIdx.x;
    const int tx   = tid % TX;
    const int ty   = tid / TX;
    const int node0 = blockIdx.x * NB;

    float bb[TN];
#pragma unroll
    for (int j = 0; j < TN; j++) bb[j] = __ldg(&b[tx * TN + j]);

    unsigned long long acc[TM][TN / 2];
#pragma unroll
    for (int m = 0; m < TM; m++)
#pragma unroll
        for (int j = 0; j < TN / 2; j++) acc[m][j] = 0ull;

    for (int kc = 0; kc < NKC; kc++) {
        const int k0 = kc * KC;
        for (int i = tid; i < NB * KC; i += 256) {
            int r = i / KC, c = i - r * KC;
            int node = node0 + r;
            inS[r * INP + c] =
                (node < N_NODES) ? __ldg(&in[(size_t)node * DIN + k0 + c]) : 0.f;
        }
        for (int i = tid; i < KC * DOUT; i += 256) {
            int r = i / DOUT, c = i - r * DOUT;
            Ws[r * SWW + c + 2 * (c >> 5)] = __ldg(&W[(size_t)(k0 + r) * DOUT + c]);
        }
        __syncthreads();

#pragma unroll
        for (int k = 0; k < KC; k++) {
            unsigned long long a2[TM];
#pragma unroll
            for (int m = 0; m < TM; m++) {
                float a = inS[(ty * TM + m) * INP + k];
                a2[m] = pack2(a, a);
            }
#pragma unroll
            for (int j = 0; j < TN / 2; j++) {
                int c = tx * TN + 2 * j;
                float2 wv = *reinterpret_cast<const float2*>(
                    &Ws[k * SWW + c + 2 * (c >> 5)]);
                unsigned long long w2 = pack2(wv.x, wv.y);
#pragma unroll
                for (int m = 0; m < TM; m++)
                    acc[m][j] = fma2(a2[m], w2, acc[m][j]);
            }
        }
        if (kc + 1 < NKC) __syncthreads();
    }

#pragma unroll
    for (int m = 0; m < TM; m++) {
        int node = node0 + ty * TM + m;
        if (node >= N_NODES) continue;
        float sc = SCALE ? __ldg(&g_dis[node]) : 1.f;
        float vals[TN];
#pragma unroll
        for (int j = 0; j < TN / 2; j++) {
            float v0, v1;
            unpack2(acc[m][j], v0, v1);
            v0 += bb[2 * j];     v1 += bb[2 * j + 1];
            v0 = v0 > 0.f ? v0 : 0.f;
            v1 = v1 > 0.f ? v1 : 0.f;
            vals[2 * j]     = v0 * sc;
            vals[2 * j + 1] = v1 * sc;
        }
        float4* o = (float4*)(out + (size_t)node * DOUT + tx * TN);
#pragma unroll
        for (int q = 0; q < TN / 4; q++)
            o[q] = make_float4(vals[4 * q], vals[4 * q + 1],
                               vals[4 * q + 2], vals[4 * q + 3]);
    }
}

// ---------------- fused dense l2+l3: 64 -> relu32 -> relu16 -----------------
__global__ void __launch_bounds__(256) k_l23(
        const float* __restrict__ in,
        const float* __restrict__ W2, const float* __restrict__ b2,
        const float* __restrict__ W3, const float* __restrict__ b3,
        float* __restrict__ out) {
    __shared__ float h1S[64 * 65];
    __shared__ float h2S[64 * 34];
    __shared__ float W2s[64 * 34];
    __shared__ float W3s[32 * 18];
    __shared__ float b2s[32];
    __shared__ float b3s[16];

    const int tid   = threadIdx.x;
    const int node0 = blockIdx.x * 64;

    // stage input h1 (64x64), weights, biases
    for (int i = tid; i < 64 * 64; i += 256) {
        int r = i >> 6, c = i & 63;
        int n = node0 + r;
        h1S[r * 65 + c] = (n < N_NODES) ? __ldg(&in[(size_t)n * 64 + c]) : 0.f;
    }
    for (int i = tid; i < 64 * 32; i += 256) {
        int r = i >> 5, c = i & 31;
        W2s[r * 34 + c] = __ldg(&W2[i]);
    }
    for (int i = tid; i < 32 * 16; i += 256) {
        int r = i >> 4, c = i & 15;
        W3s[r * 18 + c] = __ldg(&W3[i]);
    }
    if (tid < 32) b2s[tid] = __ldg(&b2[tid]);
    else if (tid < 48) b3s[tid - 32] = __ldg(&b3[tid - 32]);
    __syncthreads();

    // step 1: h2 = relu(h1 @ W2 + b2). 4 threads/node, 8 outputs each.
    {
        int r  = tid >> 2;
        int c0 = (tid & 3) * 8;
        unsigned long long acc[4] = {0ull, 0ull, 0ull, 0ull};
#pragma unroll
        for (int k = 0; k < 64; k++) {
            float a = h1S[r * 65 + k];
            unsigned long long a2 = pack2(a, a);
#pragma unroll
            for (int j = 0; j < 4; j++) {
                float2 wv = *reinterpret_cast<const float2*>(&W2s[k * 34 + c0 + 2 * j]);
                acc[j] = fma2(a2, pack2(wv.x, wv.y), acc[j]);
            }
        }
#pragma unroll
        for (int j = 0; j < 4; j++) {
            float v0, v1;
            unpack2(acc[j], v0, v1);
            v0 += b2s[c0 + 2 * j];     v1 += b2s[c0 + 2 * j + 1];
            h2S[r * 34 + c0 + 2 * j]     = v0 > 0.f ? v0 : 0.f;
            h2S[r * 34 + c0 + 2 * j + 1] = v1 > 0.f ? v1 : 0.f;
        }
    }
    __syncthreads();

    // step 2: out = relu(h2 @ W3 + b3). 4 threads/node, 4 outputs each.
    {
        int r  = tid >> 2;
        int c0 = (tid & 3) * 4;
        unsigned long long acc[2] = {0ull, 0ull};
#pragma unroll
        for (int k = 0; k < 32; k++) {
            float a = h2S[r * 34 + k];
            unsigned long long a2 = pack2(a, a);
#pragma unroll
            for (int j = 0; j < 2; j++) {
                float2 wv = *reinterpret_cast<const float2*>(&W3s[k * 18 + c0 + 2 * j]);
                acc[j] = fma2(a2, pack2(wv.x, wv.y), acc[j]);
            }
        }
        int n = node0 + r;
        if (n < N_NODES) {
            float v[4];
            unpack2(acc[0], v[0], v[1]);
            unpack2(acc[1], v[2], v[3]);
#pragma unroll
            for (int j = 0; j < 4; j++) {
                v[j] += b3s[c0 + j];
                v[j] = v[j] > 0.f ? v[j] : 0.f;
            }
            *(float4*)(out + (size_t)n * 16 + c0) = make_float4(v[0], v[1], v[2], v[3]);
        }
    }
}

// ---------------- launch ------------------------------------------------------
extern "C" void kernel_launch(void* const* d_in, const int* in_sizes, int n_in,
                              void* d_out, int out_size) {
    const float* x  = (const float*)d_in[0];
    const void*  ei = d_in[1];
    const float *W1 = (const float*)d_in[2],  *b1 = (const float*)d_in[3];
    const float *W2 = (const float*)d_in[4],  *b2 = (const float*)d_in[5];
    const float *W3 = (const float*)d_in[6],  *b3 = (const float*)d_in[7];
    const float *Wl1= (const float*)d_in[8],  *bl1= (const float*)d_in[9];
    const float *Wl2= (const float*)d_in[10], *bl2= (const float*)d_in[11];
    const float *Wl3= (const float*)d_in[12], *bl3= (const float*)d_in[13];
    float* out = (float*)d_out;

    float *feat, *agg, *actA, *actB;
    cudaGetSymbolAddress((void**)&feat, g_feat);
    cudaGetSymbolAddress((void**)&agg,  g_agg);
    cudaGetSymbolAddress((void**)&actA, g_actA);
    cudaGetSymbolAddress((void**)&actB, g_actB);

    const int TB = 256;
    const int nodeBlocks = (N_NODES + TB - 1) / TB;
    const int edgeBlocks = (N_EDGES + TB - 1) / TB;
    const int scanBlocks = (N_NODES + 1023) / 1024;
    const int convBlocks = (N_NODES + 63) / 64;

    // --- graph structure ---
    k_init<<<nodeBlocks, TB>>>(ei);
    k_hist<<<edgeBlocks, TB>>>(ei);
    k_scan1<<<scanBlocks, 1024>>>();
    k_scan2<<<1, 64>>>(scanBlocks);
    k_scan3<<<nodeBlocks, TB>>>();
    k_scatter<<<edgeBlocks, TB>>>(ei);

    // --- fused conv layers (gather + gemm) ---
    k_conv<16, 32,  true,  true ><<<convBlocks, TB>>>(x,    W1, b1, feat);
    k_conv<32, 64,  false, true ><<<convBlocks, TB>>>(feat, W2, b2, agg);
    k_conv<64, 128, false, false><<<convBlocks, TB>>>(agg,  W3, b3, actA);

    // --- dense layers ---
    k_gemm2<128, 64, false><<<convBlocks, TB>>>(actA, Wl1, bl1, actB);
    k_l23<<<convBlocks, TB>>>(actB, Wl2, bl2, Wl3, bl3, out);
}